// round 12
// baseline (speedup 1.0000x reference)
#include <cuda_runtime.h>
#include <cuda_fp16.h>
#include <cstdint>

// out[b, :] = (1/K) * sum_k table[idx[b,k], :],  V=200000 D=128 B=50000 K=32.
//
// Pass 1: f32 table -> fp16 scratch (51.2MB; evict_last stores keep it
//         L2-resident). Streaming, ~8.3 TB/s, ~19us.
// Pass 2: fp16 gather. R11 analysis: binder = LDG issue rate (4.8 cyc/LDG,
//         at the 4-cyc LSU floor) + warp issue. Fix: 2 rows per LDG.128 —
//         lanes 0-15 load row k, lanes 16-31 row k+1 (16B/lane). LDG count
//         halves; wavefronts unchanged. Pairwise __hadd2 pre-reduction per
//         half-warp, final shfl_xor(16) combine.

static constexpr long long MAX_VD4 = 6400000;   // 200000*128/4 uint2 slots
__device__ uint2 g_tab16[MAX_VD4];              // fp16 table: 51.2 MB scratch

__device__ __forceinline__ unsigned long long make_policy_el() {
    unsigned long long pol;
    asm("createpolicy.fractional.L2::evict_last.b64 %0, 1.0;" : "=l"(pol));
    return pol;
}

// ---------------- pass 1: f32 -> f16 convert (streaming) ----------------
__global__ __launch_bounds__(256) void convert_f32_to_f16(
    const float4* __restrict__ in, long long n8)   // n8 = pairs of float4
{
    long long i = (long long)blockIdx.x * blockDim.x + threadIdx.x;
    if (i >= n8) return;
    const unsigned long long pol = make_policy_el();

    float4 a = __ldcs(&in[2 * i]);
    float4 b = __ldcs(&in[2 * i + 1]);
    __half2 h0 = __floats2half2_rn(a.x, a.y);
    __half2 h1 = __floats2half2_rn(a.z, a.w);
    __half2 h2 = __floats2half2_rn(b.x, b.y);
    __half2 h3 = __floats2half2_rn(b.z, b.w);
    unsigned u0 = *reinterpret_cast<unsigned*>(&h0);
    unsigned u1 = *reinterpret_cast<unsigned*>(&h1);
    unsigned u2 = *reinterpret_cast<unsigned*>(&h2);
    unsigned u3 = *reinterpret_cast<unsigned*>(&h3);
    asm volatile("st.global.L2::cache_hint.v4.b32 [%0], {%1,%2,%3,%4}, %5;"
                 :: "l"(&g_tab16[2 * i]), "r"(u0), "r"(u1), "r"(u2), "r"(u3),
                    "l"(pol));
}

// ---------------- pass 2: fp16 gather, 2 rows per LDG.128 ----------------
__device__ __forceinline__ uint4 ldg128_pol(const char* p, unsigned long long pol) {
    uint4 v;
    asm volatile("ld.global.nc.L2::cache_hint.v4.b32 {%0,%1,%2,%3}, [%4], %5;"
                 : "=r"(v.x), "=r"(v.y), "=r"(v.z), "=r"(v.w)
                 : "l"(p), "l"(pol));
    return v;
}

__global__ __launch_bounds__(128) void gather_mean_f16_k32(
    const int* __restrict__ idx,
    float4* __restrict__ out,
    int B)
{
    const int warp = (blockIdx.x * blockDim.x + threadIdx.x) >> 5;
    const int lane = threadIdx.x & 31;
    if (warp >= B) return;

    const unsigned long long pol = make_policy_el();
    const char* tab = (const char*)g_tab16;

    // coalesced 128B streaming load of this row's 32 indices
    int my_idx = __ldcs(&idx[(long long)warp * 32 + lane]);

    const int half = lane >> 4;             // 0: even rows, 1: odd rows
    const int sub  = lane & 15;             // 16B chunk within the 256B row
    const unsigned laneOfs = (unsigned)sub * 16u;

    // 8 f32 accumulators: this lane's 8 half-columns (cols 8*sub .. 8*sub+7)
    float a0 = 0.f, a1 = 0.f, a2 = 0.f, a3 = 0.f;
    float a4 = 0.f, a5 = 0.f, a6 = 0.f, a7 = 0.f;

#pragma unroll
    for (int k = 0; k < 32; k += 4) {
        // LDG A: lanes<16 -> row k,   lanes>=16 -> row k+1
        int n0 = __shfl_sync(0xffffffffu, my_idx, k + half);
        uint4 v0 = ldg128_pol(tab + (unsigned)n0 * 256u + laneOfs, pol);
        // LDG B: lanes<16 -> row k+2, lanes>=16 -> row k+3
        int n1 = __shfl_sync(0xffffffffu, my_idx, k + 2 + half);
        uint4 v1 = ldg128_pol(tab + (unsigned)n1 * 256u + laneOfs, pol);

        // pairwise fp16 pre-reduction across the lane's two rows
        __half2 s0 = __hadd2(*reinterpret_cast<__half2*>(&v0.x),
                             *reinterpret_cast<__half2*>(&v1.x));
        __half2 s1 = __hadd2(*reinterpret_cast<__half2*>(&v0.y),
                             *reinterpret_cast<__half2*>(&v1.y));
        __half2 s2 = __hadd2(*reinterpret_cast<__half2*>(&v0.z),
                             *reinterpret_cast<__half2*>(&v1.z));
        __half2 s3 = __hadd2(*reinterpret_cast<__half2*>(&v0.w),
                             *reinterpret_cast<__half2*>(&v1.w));
        float2 f0 = __half22float2(s0);
        float2 f1 = __half22float2(s1);
        float2 f2 = __half22float2(s2);
        float2 f3 = __half22float2(s3);
        a0 += f0.x; a1 += f0.y; a2 += f1.x; a3 += f1.y;
        a4 += f2.x; a5 += f2.y; a6 += f3.x; a7 += f3.y;
    }

    // combine even-rows half with odd-rows half
    a0 += __shfl_xor_sync(0xffffffffu, a0, 16);
    a1 += __shfl_xor_sync(0xffffffffu, a1, 16);
    a2 += __shfl_xor_sync(0xffffffffu, a2, 16);
    a3 += __shfl_xor_sync(0xffffffffu, a3, 16);
    a4 += __shfl_xor_sync(0xffffffffu, a4, 16);
    a5 += __shfl_xor_sync(0xffffffffu, a5, 16);
    a6 += __shfl_xor_sync(0xffffffffu, a6, 16);
    a7 += __shfl_xor_sync(0xffffffffu, a7, 16);

    const float inv = 1.0f / 32.0f;
    // out row = 512B = 32 lanes x 16B. Lane's cols are 8*sub..8*sub+7:
    //   half 0 writes float4 slot 2*sub   (cols 8sub..8sub+3)
    //   half 1 writes float4 slot 2*sub+1 (cols 8sub+4..8sub+7)
    float4 r;
    if (half == 0) { r.x = a0; r.y = a1; r.z = a2; r.w = a3; }
    else           { r.x = a4; r.y = a5; r.z = a6; r.w = a7; }
    r.x *= inv; r.y *= inv; r.z *= inv; r.w *= inv;
    __stcs(&out[(long long)warp * 32 + 2 * sub + half], r);
}

// ---------------- fallback: f32 path (K != 32 or oversized table) --------
__global__ __launch_bounds__(256) void gather_mean_generic(
    const float4* __restrict__ table,
    const int* __restrict__ idx,
    float4* __restrict__ out,
    int B, int K)
{
    const int warp = (blockIdx.x * blockDim.x + threadIdx.x) >> 5;
    const int lane = threadIdx.x & 31;
    if (warp >= B) return;

    const int* row_idx = idx + (long long)warp * K;

    float4 acc = make_float4(0.f, 0.f, 0.f, 0.f);
    int k = 0;
    for (; k + 8 <= K; k += 8) {
        float4 v[8];
#pragma unroll
        for (int j = 0; j < 8; ++j) {
            int n = __ldg(&row_idx[k + j]);
            v[j] = __ldg(&table[(long long)n * 32 + lane]);
        }
#pragma unroll
        for (int j = 0; j < 8; ++j) {
            acc.x += v[j].x; acc.y += v[j].y;
            acc.z += v[j].z; acc.w += v[j].w;
        }
    }
    for (; k < K; ++k) {
        int n = row_idx[k];
        float4 v = __ldg(&table[(long long)n * 32 + lane]);
        acc.x += v.x; acc.y += v.y; acc.z += v.z; acc.w += v.w;
    }

    const float inv = 1.0f / (float)K;
    acc.x *= inv; acc.y *= inv; acc.z *= inv; acc.w *= inv;
    out[(long long)warp * 32 + lane] = acc;
}

extern "C" void kernel_launch(void* const* d_in, const int* in_sizes, int n_in,
                              void* d_out, int out_size)
{
    const int B = out_size / 128;                   // rows of output
    const int K = (B > 0) ? (in_sizes[1] / B) : 0;
    const long long VD = (long long)in_sizes[0];    // table element count

    if (K == 32 && VD % 8 == 0 && VD / 4 <= MAX_VD4 && (VD & 127) == 0) {
        const float4* table = (const float4*)d_in[0];
        const int*    idx   = (const int*)d_in[1];
        float4*       out   = (float4*)d_out;

        const long long n8 = VD / 8;                // 2 float4 per thread
        const int cblocks = (int)((n8 + 255) / 256);
        convert_f32_to_f16<<<cblocks, 256>>>(table, n8);

        const int gblocks = (B + 3) / 4;            // 4 warps/block, 1 row/warp
        gather_mean_f16_k32<<<gblocks, 128>>>(idx, out, B);
    } else {
        const float4* table = (const float4*)d_in[0];
        const int*    idx   = (const int*)d_in[1];
        float4*       out   = (float4*)d_out;
        const int blocks = (B + 7) / 8;
        gather_mean_generic<<<blocks, 256>>>(table, idx, out, B, K);
    }
}

// round 13
// speedup vs baseline: 1.0484x; 1.0484x over previous
#include <cuda_runtime.h>
#include <cuda_fp16.h>
#include <cstdint>

// out[b, :] = (1/K) * sum_k table[idx[b,k], :],  V=200000 D=128 B=50000 K=32.
//
// Pass 1: f32 table -> fp16 scratch (51.2MB; evict_last stores keep it
//         L2-resident). Streaming, ~8.3 TB/s.
// Pass 2: fp16 gather, 2 rows per LDG.128 (lanes 0-15 row k, lanes 16-31
//         row k+1; 16B/lane). R12 lesson: full unroll -> 48 regs -> occ 55%.
//         Fix: #pragma unroll 2 caps live LDG buffers at 4 -> regs ~38,
//         occ ~80%, while keeping the halved LDG/shfl count per row.

static constexpr long long MAX_VD4 = 6400000;   // 200000*128/4 uint2 slots
__device__ uint2 g_tab16[MAX_VD4];              // fp16 table: 51.2 MB scratch

__device__ __forceinline__ unsigned long long make_policy_el() {
    unsigned long long pol;
    asm("createpolicy.fractional.L2::evict_last.b64 %0, 1.0;" : "=l"(pol));
    return pol;
}

// ---------------- pass 1: f32 -> f16 convert (streaming) ----------------
__global__ __launch_bounds__(256) void convert_f32_to_f16(
    const float4* __restrict__ in, long long n8)   // n8 = pairs of float4
{
    long long i = (long long)blockIdx.x * blockDim.x + threadIdx.x;
    if (i >= n8) return;
    const unsigned long long pol = make_policy_el();

    float4 a = __ldcs(&in[2 * i]);
    float4 b = __ldcs(&in[2 * i + 1]);
    __half2 h0 = __floats2half2_rn(a.x, a.y);
    __half2 h1 = __floats2half2_rn(a.z, a.w);
    __half2 h2 = __floats2half2_rn(b.x, b.y);
    __half2 h3 = __floats2half2_rn(b.z, b.w);
    unsigned u0 = *reinterpret_cast<unsigned*>(&h0);
    unsigned u1 = *reinterpret_cast<unsigned*>(&h1);
    unsigned u2 = *reinterpret_cast<unsigned*>(&h2);
    unsigned u3 = *reinterpret_cast<unsigned*>(&h3);
    asm volatile("st.global.L2::cache_hint.v4.b32 [%0], {%1,%2,%3,%4}, %5;"
                 :: "l"(&g_tab16[2 * i]), "r"(u0), "r"(u1), "r"(u2), "r"(u3),
                    "l"(pol));
}

// ---------------- pass 2: fp16 gather, 2 rows per LDG.128 ----------------
__device__ __forceinline__ uint4 ldg128_pol(const char* p, unsigned long long pol) {
    uint4 v;
    asm volatile("ld.global.nc.L2::cache_hint.v4.b32 {%0,%1,%2,%3}, [%4], %5;"
                 : "=r"(v.x), "=r"(v.y), "=r"(v.z), "=r"(v.w)
                 : "l"(p), "l"(pol));
    return v;
}

__global__ __launch_bounds__(128) void gather_mean_f16_k32(
    const int* __restrict__ idx,
    float4* __restrict__ out,
    int B)
{
    const int warp = (blockIdx.x * blockDim.x + threadIdx.x) >> 5;
    const int lane = threadIdx.x & 31;
    if (warp >= B) return;

    const unsigned long long pol = make_policy_el();
    const char* tab = (const char*)g_tab16;

    // coalesced 128B streaming load of this row's 32 indices
    int my_idx = __ldcs(&idx[(long long)warp * 32 + lane]);

    const int half = lane >> 4;             // 0: even rows, 1: odd rows
    const int sub  = lane & 15;             // 16B chunk within the 256B row
    const unsigned laneOfs = (unsigned)sub * 16u;

    // 8 f32 accumulators: this lane's 8 half-columns (cols 8*sub .. 8*sub+7)
    float a0 = 0.f, a1 = 0.f, a2 = 0.f, a3 = 0.f;
    float a4 = 0.f, a5 = 0.f, a6 = 0.f, a7 = 0.f;

#pragma unroll 2
    for (int k = 0; k < 32; k += 4) {
        // LDG A: lanes<16 -> row k,   lanes>=16 -> row k+1
        int n0 = __shfl_sync(0xffffffffu, my_idx, k + half);
        uint4 v0 = ldg128_pol(tab + (unsigned)n0 * 256u + laneOfs, pol);
        // LDG B: lanes<16 -> row k+2, lanes>=16 -> row k+3
        int n1 = __shfl_sync(0xffffffffu, my_idx, k + 2 + half);
        uint4 v1 = ldg128_pol(tab + (unsigned)n1 * 256u + laneOfs, pol);

        // pairwise fp16 pre-reduction across the lane's two rows
        __half2 s0 = __hadd2(*reinterpret_cast<__half2*>(&v0.x),
                             *reinterpret_cast<__half2*>(&v1.x));
        __half2 s1 = __hadd2(*reinterpret_cast<__half2*>(&v0.y),
                             *reinterpret_cast<__half2*>(&v1.y));
        __half2 s2 = __hadd2(*reinterpret_cast<__half2*>(&v0.z),
                             *reinterpret_cast<__half2*>(&v1.z));
        __half2 s3 = __hadd2(*reinterpret_cast<__half2*>(&v0.w),
                             *reinterpret_cast<__half2*>(&v1.w));
        float2 f0 = __half22float2(s0);
        float2 f1 = __half22float2(s1);
        float2 f2 = __half22float2(s2);
        float2 f3 = __half22float2(s3);
        a0 += f0.x; a1 += f0.y; a2 += f1.x; a3 += f1.y;
        a4 += f2.x; a5 += f2.y; a6 += f3.x; a7 += f3.y;
    }

    // combine even-rows half with odd-rows half
    a0 += __shfl_xor_sync(0xffffffffu, a0, 16);
    a1 += __shfl_xor_sync(0xffffffffu, a1, 16);
    a2 += __shfl_xor_sync(0xffffffffu, a2, 16);
    a3 += __shfl_xor_sync(0xffffffffu, a3, 16);
    a4 += __shfl_xor_sync(0xffffffffu, a4, 16);
    a5 += __shfl_xor_sync(0xffffffffu, a5, 16);
    a6 += __shfl_xor_sync(0xffffffffu, a6, 16);
    a7 += __shfl_xor_sync(0xffffffffu, a7, 16);

    const float inv = 1.0f / 32.0f;
    // out row = 512B = 32 lanes x 16B. Lane's cols are 8*sub..8*sub+7:
    //   half 0 writes float4 slot 2*sub   (cols 8sub..8sub+3)
    //   half 1 writes float4 slot 2*sub+1 (cols 8sub+4..8sub+7)
    float4 r;
    if (half == 0) { r.x = a0; r.y = a1; r.z = a2; r.w = a3; }
    else           { r.x = a4; r.y = a5; r.z = a6; r.w = a7; }
    r.x *= inv; r.y *= inv; r.z *= inv; r.w *= inv;
    __stcs(&out[(long long)warp * 32 + 2 * sub + half], r);
}

// ---------------- fallback: f32 path (K != 32 or oversized table) --------
__global__ __launch_bounds__(256) void gather_mean_generic(
    const float4* __restrict__ table,
    const int* __restrict__ idx,
    float4* __restrict__ out,
    int B, int K)
{
    const int warp = (blockIdx.x * blockDim.x + threadIdx.x) >> 5;
    const int lane = threadIdx.x & 31;
    if (warp >= B) return;

    const int* row_idx = idx + (long long)warp * K;

    float4 acc = make_float4(0.f, 0.f, 0.f, 0.f);
    int k = 0;
    for (; k + 8 <= K; k += 8) {
        float4 v[8];
#pragma unroll
        for (int j = 0; j < 8; ++j) {
            int n = __ldg(&row_idx[k + j]);
            v[j] = __ldg(&table[(long long)n * 32 + lane]);
        }
#pragma unroll
        for (int j = 0; j < 8; ++j) {
            acc.x += v[j].x; acc.y += v[j].y;
            acc.z += v[j].z; acc.w += v[j].w;
        }
    }
    for (; k < K; ++k) {
        int n = row_idx[k];
        float4 v = __ldg(&table[(long long)n * 32 + lane]);
        acc.x += v.x; acc.y += v.y; acc.z += v.z; acc.w += v.w;
    }

    const float inv = 1.0f / (float)K;
    acc.x *= inv; acc.y *= inv; acc.z *= inv; acc.w *= inv;
    out[(long long)warp * 32 + lane] = acc;
}

extern "C" void kernel_launch(void* const* d_in, const int* in_sizes, int n_in,
                              void* d_out, int out_size)
{
    const int B = out_size / 128;                   // rows of output
    const int K = (B > 0) ? (in_sizes[1] / B) : 0;
    const long long VD = (long long)in_sizes[0];    // table element count

    if (K == 32 && VD % 8 == 0 && VD / 4 <= MAX_VD4 && (VD & 127) == 0) {
        const float4* table = (const float4*)d_in[0];
        const int*    idx   = (const int*)d_in[1];
        float4*       out   = (float4*)d_out;

        const long long n8 = VD / 8;                // 2 float4 per thread
        const int cblocks = (int)((n8 + 255) / 256);
        convert_f32_to_f16<<<cblocks, 256>>>(table, n8);

        const int gblocks = (B + 3) / 4;            // 4 warps/block, 1 row/warp
        gather_mean_f16_k32<<<gblocks, 128>>>(idx, out, B);
    } else {
        const float4* table = (const float4*)d_in[0];
        const int*    idx   = (const int*)d_in[1];
        float4*       out   = (float4*)d_out;
        const int blocks = (B + 7) / 8;
        gather_mean_generic<<<blocks, 256>>>(table, idx, out, B, K);
    }
}